// round 1
// baseline (speedup 1.0000x reference)
#include <cuda_runtime.h>
#include <math.h>

#define NN 50000
#define EPS_BN 1e-5f
#define SLOPE 0.01f

// ---------------- scratch (static device memory; no allocs) ----------------
__device__ float g_deg[NN];
__device__ float g_dinv[NN];
__device__ float g_acc1[NN * 64];
__device__ float g_h1[(size_t)NN * 128];
__device__ float g_u2[NN * 64];
__device__ float g_acc2[NN * 64];
__device__ float g_u3[NN * 64];
__device__ float g_acc3[NN * 64];
// stats layout:
// [0:128) sum1  [128:256) sumsq1  [256:384) scale1  [384:512) shift1
// [512:576) sum2 [576:640) sumsq2 [640:704) scale2  [704:768) shift2(+b2 folded)
__device__ float g_stats[1024];

__device__ __forceinline__ void red_add_v4(float* a, float x, float y, float z, float w) {
    asm volatile("red.global.add.v4.f32 [%0], {%1,%2,%3,%4};"
                 :: "l"(a), "f"(x), "f"(y), "f"(z), "f"(w) : "memory");
}

__device__ __forceinline__ float lrelu(float v) { return v > 0.f ? v : SLOPE * v; }

// ---------------- small kernels ----------------
__global__ void k_init() {
    int i = blockIdx.x * blockDim.x + threadIdx.x;
    if (i < NN) g_deg[i] = 1.0f;       // self loop
    if (i < 1024) g_stats[i] = 0.0f;
}

__global__ void k_deg(const int* __restrict__ dst, int nE) {
    int e = blockIdx.x * blockDim.x + threadIdx.x;
    if (e < nE) atomicAdd(&g_deg[dst[e]], 1.0f);
}

// dinv + acc1 init (self-loop term u1[i] = x[i]*dinv[i])
__global__ void k_prep(const float* __restrict__ x) {
    int t = blockIdx.x * blockDim.x + threadIdx.x;
    if (t >= NN * 16) return;
    int i = t >> 4;
    float d = rsqrtf(g_deg[i]);
    if ((t & 15) == 0) g_dinv[i] = d;
    float4 v = __ldg((const float4*)x + t);
    ((float4*)g_acc1)[t] = make_float4(v.x * d, v.y * d, v.z * d, v.w * d);
}

// layer-1 scatter: acc1[dst] += x[src]*dinv[src]   (64 ch, 16 lanes/edge)
__global__ void k_scatter1(const float* __restrict__ x,
                           const int* __restrict__ src, const int* __restrict__ dst, int nE) {
    int t = blockIdx.x * blockDim.x + threadIdx.x;
    if (t >= nE * 16) return;
    int e = t >> 4, c = t & 15;
    int s = __ldg(&src[e]), d = __ldg(&dst[e]);
    float ds = __ldg((const float*)&g_dinv[s]);
    float4 v = __ldg((const float4*)x + s * 16 + c);
    red_add_v4(g_acc1 + d * 64 + c * 4, v.x * ds, v.y * ds, v.z * ds, v.w * ds);
}

// generic scatter for layers 2/3 (u already pre-scaled by dinv)
template <int LAYER>
__global__ void k_scatter(const int* __restrict__ src, const int* __restrict__ dst, int nE) {
    int t = blockIdx.x * blockDim.x + threadIdx.x;
    if (t >= nE * 16) return;
    int e = t >> 4, c = t & 15;
    int s = __ldg(&src[e]), d = __ldg(&dst[e]);
    const float* u = (LAYER == 2) ? g_u2 : g_u3;
    float* acc = (LAYER == 2) ? g_acc2 : g_acc3;
    float4 v = __ldg((const float4*)u + s * 16 + c);
    red_add_v4(acc + d * 64 + c * 4, v.x, v.y, v.z, v.w);
}

// ---------------- fused GEMM ----------------
// MODE 1: in = dinv*acc1 (64) -> W1 -> +b1 -> store h1, BN stats to g_stats[0],[128]
// MODE 2: in = leaky(h1*scale1+shift1) (128) -> W2 -> *dinv -> store u2, acc2
// MODE 3: in = leaky(dinv*acc2*scale2+shift2) (64) -> W3 -> *dinv -> store u3, acc3
template <int K, int NC, int RPT, int MODE>
__global__ void __launch_bounds__(256) k_gemm(const float* __restrict__ Wg,
                                              const float* __restrict__ bias) {
    constexpr int R = 16 * RPT;
    constexpr int CPT = NC / 16;
    constexpr int KQ = K / 4;
    __shared__ float Ws[K * NC];
    __shared__ float Is[R * K];

    const int tid = threadIdx.x;
    const int row0 = blockIdx.x * R;

    // stage W
    {
        const float4* Wg4 = (const float4*)Wg;
        float4* Ws4 = (float4*)Ws;
        #pragma unroll
        for (int i = tid; i < K * NC / 4; i += 256) Ws4[i] = __ldg(Wg4 + i);
    }
    // stage input tile with fused transform
    {
        float4* Is4 = (float4*)Is;
        #pragma unroll
        for (int i = tid; i < R * KQ; i += 256) {
            int r = i / KQ, kq = i % KQ;
            int gr = row0 + r;
            float4 v = make_float4(0.f, 0.f, 0.f, 0.f);
            if (gr < NN) {
                if (MODE == 1) {
                    float4 a = __ldg((const float4*)g_acc1 + gr * 16 + kq);
                    float d = __ldg((const float*)&g_dinv[gr]);
                    v = make_float4(a.x * d, a.y * d, a.z * d, a.w * d);
                } else if (MODE == 2) {
                    float4 h = __ldg((const float4*)g_h1 + (size_t)gr * 32 + kq);
                    float4 sc = __ldg((const float4*)(g_stats + 256) + kq);
                    float4 sh = __ldg((const float4*)(g_stats + 384) + kq);
                    v.x = lrelu(fmaf(h.x, sc.x, sh.x));
                    v.y = lrelu(fmaf(h.y, sc.y, sh.y));
                    v.z = lrelu(fmaf(h.z, sc.z, sh.z));
                    v.w = lrelu(fmaf(h.w, sc.w, sh.w));
                } else {
                    float4 a = __ldg((const float4*)g_acc2 + gr * 16 + kq);
                    float d = __ldg((const float*)&g_dinv[gr]);
                    float4 sc = __ldg((const float4*)(g_stats + 640) + kq);
                    float4 sh = __ldg((const float4*)(g_stats + 704) + kq);
                    v.x = lrelu(fmaf(a.x * d, sc.x, sh.x));
                    v.y = lrelu(fmaf(a.y * d, sc.y, sh.y));
                    v.z = lrelu(fmaf(a.z * d, sc.z, sh.z));
                    v.w = lrelu(fmaf(a.w * d, sc.w, sh.w));
                }
            }
            Is4[i] = v;
        }
    }
    __syncthreads();

    const int ct = tid & 15, rt = tid >> 4;
    float acc[RPT][CPT];
    #pragma unroll
    for (int j = 0; j < RPT; j++)
        #pragma unroll
        for (int c = 0; c < CPT; c++) acc[j][c] = 0.f;

    const float* isbase = Is + (rt * RPT) * K;
    #pragma unroll 4
    for (int k4 = 0; k4 < K / 4; ++k4) {
        float a[RPT][4];
        #pragma unroll
        for (int j = 0; j < RPT; j++) {
            float4 t4 = *(const float4*)(isbase + j * K + k4 * 4);
            a[j][0] = t4.x; a[j][1] = t4.y; a[j][2] = t4.z; a[j][3] = t4.w;
        }
        #pragma unroll
        for (int kk = 0; kk < 4; kk++) {
            float w[CPT];
            const float4* wr = (const float4*)(Ws + (k4 * 4 + kk) * NC + ct * CPT);
            #pragma unroll
            for (int q = 0; q < CPT / 4; q++) {
                float4 w4 = wr[q];
                w[q * 4 + 0] = w4.x; w[q * 4 + 1] = w4.y;
                w[q * 4 + 2] = w4.z; w[q * 4 + 3] = w4.w;
            }
            #pragma unroll
            for (int j = 0; j < RPT; j++)
                #pragma unroll
                for (int c = 0; c < CPT; c++)
                    acc[j][c] = fmaf(a[j][kk], w[c], acc[j][c]);
        }
    }

    if (MODE == 1) {
        float bl[CPT];
        #pragma unroll
        for (int c = 0; c < CPT; c++) bl[c] = __ldg(&bias[ct * CPT + c]);
        #pragma unroll
        for (int j = 0; j < RPT; j++) {
            int gr = row0 + rt * RPT + j;
            if (gr < NN) {
                #pragma unroll
                for (int c = 0; c < CPT; c++) acc[j][c] += bl[c];
                float4* o = (float4*)(g_h1 + (size_t)gr * NC + ct * CPT);
                #pragma unroll
                for (int q = 0; q < CPT / 4; q++)
                    o[q] = make_float4(acc[j][q * 4 + 0], acc[j][q * 4 + 1],
                                       acc[j][q * 4 + 2], acc[j][q * 4 + 3]);
            } else {
                #pragma unroll
                for (int c = 0; c < CPT; c++) acc[j][c] = 0.f;
            }
        }
        // BN stats: reuse Is as reduction buffer
        __syncthreads();
        float* ssum = Is;
        float* ssq = Is + NC;
        if (tid < 2 * NC) Is[tid] = 0.f;
        __syncthreads();
        #pragma unroll
        for (int c = 0; c < CPT; c++) {
            float sv = 0.f, sq = 0.f;
            #pragma unroll
            for (int j = 0; j < RPT; j++) { sv += acc[j][c]; sq += acc[j][c] * acc[j][c]; }
            atomicAdd(&ssum[ct * CPT + c], sv);
            atomicAdd(&ssq[ct * CPT + c], sq);
        }
        __syncthreads();
        if (tid < NC) {
            atomicAdd(&g_stats[tid], ssum[tid]);
            atomicAdd(&g_stats[128 + tid], ssq[tid]);
        }
    } else {
        float* o0 = (MODE == 2) ? g_u2 : g_u3;
        float* o1 = (MODE == 2) ? g_acc2 : g_acc3;
        #pragma unroll
        for (int j = 0; j < RPT; j++) {
            int gr = row0 + rt * RPT + j;
            if (gr >= NN) continue;
            float d = __ldg((const float*)&g_dinv[gr]);
            float4 v = make_float4(acc[j][0] * d, acc[j][1] * d, acc[j][2] * d, acc[j][3] * d);
            ((float4*)(o0 + (size_t)gr * NC))[ct] = v;
            ((float4*)(o1 + (size_t)gr * NC))[ct] = v;
        }
    }
}

__global__ void k_final1(const float* __restrict__ g1, const float* __restrict__ be1) {
    int c = threadIdx.x;  // 128
    float mean = g_stats[c] * (1.0f / NN);
    float var = g_stats[128 + c] * (1.0f / NN) - mean * mean;
    float sc = rsqrtf(var + EPS_BN) * __ldg(&g1[c]);
    g_stats[256 + c] = sc;
    g_stats[384 + c] = __ldg(&be1[c]) - mean * sc;
}

// stats over h2 = dinv*acc2 + b2
__global__ void k_stats2(const float* __restrict__ b2) {
    __shared__ float ssum[64], ssq[64];
    int tid = threadIdx.x;
    if (tid < 64) ssum[tid] = 0.f;
    else if (tid < 128) ssq[tid - 64] = 0.f;
    __syncthreads();
    int c4 = tid & 15;
    int rs = tid >> 4;
    float4 b = __ldg((const float4*)b2 + c4);
    float4 s = make_float4(0, 0, 0, 0), q = make_float4(0, 0, 0, 0);
    for (int r = blockIdx.x * 16 + rs; r < NN; r += gridDim.x * 16) {
        float d = g_dinv[r];
        float4 a = ((const float4*)g_acc2)[r * 16 + c4];
        float vx = fmaf(a.x, d, b.x), vy = fmaf(a.y, d, b.y);
        float vz = fmaf(a.z, d, b.z), vw = fmaf(a.w, d, b.w);
        s.x += vx; s.y += vy; s.z += vz; s.w += vw;
        q.x += vx * vx; q.y += vy * vy; q.z += vz * vz; q.w += vw * vw;
    }
    atomicAdd(&ssum[c4 * 4 + 0], s.x); atomicAdd(&ssum[c4 * 4 + 1], s.y);
    atomicAdd(&ssum[c4 * 4 + 2], s.z); atomicAdd(&ssum[c4 * 4 + 3], s.w);
    atomicAdd(&ssq[c4 * 4 + 0], q.x);  atomicAdd(&ssq[c4 * 4 + 1], q.y);
    atomicAdd(&ssq[c4 * 4 + 2], q.z);  atomicAdd(&ssq[c4 * 4 + 3], q.w);
    __syncthreads();
    if (tid < 64) {
        atomicAdd(&g_stats[512 + tid], ssum[tid]);
        atomicAdd(&g_stats[576 + tid], ssq[tid]);
    }
}

__global__ void k_final2(const float* __restrict__ g2, const float* __restrict__ be2,
                         const float* __restrict__ b2) {
    int c = threadIdx.x;  // 64
    float mean = g_stats[512 + c] * (1.0f / NN);
    float var = g_stats[576 + c] * (1.0f / NN) - mean * mean;
    float sc = rsqrtf(var + EPS_BN) * __ldg(&g2[c]);
    g_stats[640 + c] = sc;
    // fold +b2 into shift:  (dinv*acc2 + b2 - mean)*rstd*g + be
    g_stats[704 + c] = __ldg(&be2[c]) + (__ldg(&b2[c]) - mean) * sc;
}

__global__ void k_out(float* __restrict__ out, const float* __restrict__ b3) {
    int t = blockIdx.x * blockDim.x + threadIdx.x;
    if (t >= NN * 16) return;
    int i = t >> 4, c4 = t & 15;
    float d = g_dinv[i];
    float4 a = ((const float4*)g_acc3)[t];
    float4 b = __ldg((const float4*)b3 + c4);
    ((float4*)out)[t] = make_float4(fmaf(a.x, d, b.x), fmaf(a.y, d, b.y),
                                    fmaf(a.z, d, b.z), fmaf(a.w, d, b.w));
}

// ---------------- launcher ----------------
extern "C" void kernel_launch(void* const* d_in, const int* in_sizes, int n_in,
                              void* d_out, int out_size) {
    const float* x  = (const float*)d_in[0];
    const int* ei   = (const int*)d_in[1];
    const float* W1 = (const float*)d_in[2];
    const float* b1 = (const float*)d_in[3];
    const float* g1 = (const float*)d_in[4];
    const float* be1= (const float*)d_in[5];
    const float* W2 = (const float*)d_in[6];
    const float* b2 = (const float*)d_in[7];
    const float* g2 = (const float*)d_in[8];
    const float* be2= (const float*)d_in[9];
    const float* W3 = (const float*)d_in[10];
    const float* b3 = (const float*)d_in[11];

    const int nE = in_sizes[1] / 2;
    const int* src = ei;
    const int* dst = ei + nE;

    k_init<<<(NN + 255) / 256, 256>>>();
    k_deg<<<(nE + 255) / 256, 256>>>(dst, nE);
    k_prep<<<(NN * 16 + 255) / 256, 256>>>(x);

    // layer 1 (aggregate at 64 ch BEFORE GEMM: A(xW) == (Ax)W)
    k_scatter1<<<(nE * 16 + 255) / 256, 256>>>(x, src, dst, nE);
    k_gemm<64, 128, 4, 1><<<(NN + 63) / 64, 256>>>(W1, b1);
    k_final1<<<1, 128>>>(g1, be1);

    // layer 2
    k_gemm<128, 64, 2, 2><<<(NN + 31) / 32, 256>>>(W2, nullptr);
    k_scatter<2><<<(nE * 16 + 255) / 256, 256>>>(src, dst, nE);
    k_stats2<<<256, 256>>>(b2);
    k_final2<<<1, 64>>>(g2, be2, b2);

    // layer 3
    k_gemm<64, 64, 4, 3><<<(NN + 63) / 64, 256>>>(W3, nullptr);
    k_scatter<3><<<(nE * 16 + 255) / 256, 256>>>(src, dst, nE);

    k_out<<<(NN * 16 + 255) / 256, 256>>>((float*)d_out, b3);
}

// round 2
// speedup vs baseline: 1.3630x; 1.3630x over previous
#include <cuda_runtime.h>
#include <math.h>

#define NN 50000
#define NE_MAX 800000
#define NBLK 196          // ceil(NN/256)
#define EPS_BN 1e-5f
#define SLOPE 0.01f

// ---------------- scratch (static device memory; no allocs) ----------------
__device__ int   g_degi[NN];
__device__ int   g_scan[NN];
__device__ int   g_bsum[256];
__device__ int   g_boff[256];
__device__ int   g_start[NN];
__device__ int   g_end[NN];
__device__ int   g_cur[NN];
__device__ int   g_csr[NE_MAX];
__device__ float g_dinv[NN];
__device__ float g_u1[NN * 64];      // x * dinv  (pre-scaled layer-1 messages)
__device__ float g_acc1[NN * 64];
__device__ float g_h1[(size_t)NN * 128];
__device__ float g_u2[NN * 64];
__device__ float g_acc2[NN * 64];
__device__ float g_u3[NN * 64];
// stats layout:
// [0:128) sum1  [128:256) sumsq1  [256:384) scale1  [384:512) shift1
// [512:576) sum2 [576:640) sumsq2 [640:704) scale2  [704:768) shift2(+b2 folded)
__device__ float g_stats[1024];

__device__ __forceinline__ float lrelu(float v) { return v > 0.f ? v : SLOPE * v; }

// ---------------- CSR build ----------------
__global__ void k_init() {
    int i = blockIdx.x * blockDim.x + threadIdx.x;
    if (i < NN) g_degi[i] = 0;
    if (i < 1024) g_stats[i] = 0.0f;
}

__global__ void k_deg(const int* __restrict__ dst, int nE) {
    int e = blockIdx.x * blockDim.x + threadIdx.x;
    if (e < nE) atomicAdd(&g_degi[dst[e]], 1);
}

__global__ void k_scan1() {
    __shared__ int sh[256];
    int tid = threadIdx.x;
    int i = blockIdx.x * 256 + tid;
    int v = (i < NN) ? g_degi[i] : 0;
    sh[tid] = v;
    __syncthreads();
    #pragma unroll
    for (int off = 1; off < 256; off <<= 1) {
        int t = (tid >= off) ? sh[tid - off] : 0;
        __syncthreads();
        sh[tid] += t;
        __syncthreads();
    }
    if (i < NN) g_scan[i] = sh[tid];          // inclusive within block
    if (tid == 255) g_bsum[blockIdx.x] = sh[255];
}

__global__ void k_scan2() {
    __shared__ int sh[256];
    int tid = threadIdx.x;
    int v = (tid < NBLK) ? g_bsum[tid] : 0;
    sh[tid] = v;
    __syncthreads();
    #pragma unroll
    for (int off = 1; off < 256; off <<= 1) {
        int t = (tid >= off) ? sh[tid - off] : 0;
        __syncthreads();
        sh[tid] += t;
        __syncthreads();
    }
    g_boff[tid] = sh[tid] - v;                 // exclusive
}

__global__ void k_scan3() {
    int i = blockIdx.x * 256 + threadIdx.x;
    if (i >= NN) return;
    int inc = g_scan[i] + g_boff[blockIdx.x];
    int deg = g_degi[i];
    g_end[i] = inc;
    g_start[i] = inc - deg;
    g_cur[i] = inc - deg;
}

__global__ void k_fill(const int* __restrict__ src, const int* __restrict__ dst, int nE) {
    int e = blockIdx.x * blockDim.x + threadIdx.x;
    if (e >= nE) return;
    int d = __ldg(&dst[e]);
    int pos = atomicAdd(&g_cur[d], 1);
    g_csr[pos] = __ldg(&src[e]);
}

// dinv + u1 = x*dinv  (self-loop term included implicitly by gather)
__global__ void k_prep(const float* __restrict__ x) {
    int t = blockIdx.x * blockDim.x + threadIdx.x;
    if (t >= NN * 16) return;
    int i = t >> 4;
    float d = rsqrtf((float)(g_degi[i] + 1));   // +1 self loop
    if ((t & 15) == 0) g_dinv[i] = d;
    float4 v = __ldg((const float4*)x + t);
    ((float4*)g_u1)[t] = make_float4(v.x * d, v.y * d, v.z * d, v.w * d);
}

// ---------------- gather (replaces atomic scatter) ----------------
// 16 lanes per node, each lane owns 4 channels. acc = u[self] + sum u[neighbors].
template <int MODE>
__global__ void __launch_bounds__(256) k_gather(float* __restrict__ out,
                                                const float* __restrict__ b3) {
    int t = blockIdx.x * blockDim.x + threadIdx.x;
    if (t >= NN * 16) return;
    int g = t >> 4, lane = t & 15;
    const float* u = (MODE == 1) ? g_u1 : (MODE == 2) ? g_u2 : g_u3;

    float4 acc = __ldg((const float4*)u + t);   // self-loop term
    int j = __ldg(&g_start[g]);
    int end = __ldg(&g_end[g]);
    for (; j + 1 < end; j += 2) {
        int s0 = __ldg(&g_csr[j]);
        int s1 = __ldg(&g_csr[j + 1]);
        float4 v0 = __ldg((const float4*)u + s0 * 16 + lane);
        float4 v1 = __ldg((const float4*)u + s1 * 16 + lane);
        acc.x += v0.x + v1.x; acc.y += v0.y + v1.y;
        acc.z += v0.z + v1.z; acc.w += v0.w + v1.w;
    }
    if (j < end) {
        int s0 = __ldg(&g_csr[j]);
        float4 v0 = __ldg((const float4*)u + s0 * 16 + lane);
        acc.x += v0.x; acc.y += v0.y; acc.z += v0.z; acc.w += v0.w;
    }

    if (MODE == 1) {
        ((float4*)g_acc1)[t] = acc;
    } else if (MODE == 2) {
        ((float4*)g_acc2)[t] = acc;
    } else {
        float d = g_dinv[g];
        float4 b = __ldg((const float4*)b3 + lane);
        ((float4*)out)[t] = make_float4(fmaf(acc.x, d, b.x), fmaf(acc.y, d, b.y),
                                        fmaf(acc.z, d, b.z), fmaf(acc.w, d, b.w));
    }
}

// ---------------- fused GEMM ----------------
// MODE 1: in = dinv*acc1 (64) -> W1 -> +b1 -> store h1, BN stats
// MODE 2: in = leaky(h1*scale1+shift1) (128) -> W2 -> *dinv -> store u2
// MODE 3: in = leaky(dinv*acc2*scale2+shift2) (64) -> W3 -> *dinv -> store u3
template <int K, int NC, int RPT, int MODE>
__global__ void __launch_bounds__(256) k_gemm(const float* __restrict__ Wg,
                                              const float* __restrict__ bias) {
    constexpr int R = 16 * RPT;
    constexpr int CPT = NC / 16;
    constexpr int KQ = K / 4;
    __shared__ float Ws[K * NC];
    __shared__ float Is[R * K];

    const int tid = threadIdx.x;
    const int row0 = blockIdx.x * R;

    {
        const float4* Wg4 = (const float4*)Wg;
        float4* Ws4 = (float4*)Ws;
        #pragma unroll
        for (int i = tid; i < K * NC / 4; i += 256) Ws4[i] = __ldg(Wg4 + i);
    }
    {
        float4* Is4 = (float4*)Is;
        #pragma unroll
        for (int i = tid; i < R * KQ; i += 256) {
            int r = i / KQ, kq = i % KQ;
            int gr = row0 + r;
            float4 v = make_float4(0.f, 0.f, 0.f, 0.f);
            if (gr < NN) {
                if (MODE == 1) {
                    float4 a = __ldg((const float4*)g_acc1 + gr * 16 + kq);
                    float d = __ldg((const float*)&g_dinv[gr]);
                    v = make_float4(a.x * d, a.y * d, a.z * d, a.w * d);
                } else if (MODE == 2) {
                    float4 h = __ldg((const float4*)g_h1 + (size_t)gr * 32 + kq);
                    float4 sc = __ldg((const float4*)(g_stats + 256) + kq);
                    float4 sh = __ldg((const float4*)(g_stats + 384) + kq);
                    v.x = lrelu(fmaf(h.x, sc.x, sh.x));
                    v.y = lrelu(fmaf(h.y, sc.y, sh.y));
                    v.z = lrelu(fmaf(h.z, sc.z, sh.z));
                    v.w = lrelu(fmaf(h.w, sc.w, sh.w));
                } else {
                    float4 a = __ldg((const float4*)g_acc2 + gr * 16 + kq);
                    float d = __ldg((const float*)&g_dinv[gr]);
                    float4 sc = __ldg((const float4*)(g_stats + 640) + kq);
                    float4 sh = __ldg((const float4*)(g_stats + 704) + kq);
                    v.x = lrelu(fmaf(a.x * d, sc.x, sh.x));
                    v.y = lrelu(fmaf(a.y * d, sc.y, sh.y));
                    v.z = lrelu(fmaf(a.z * d, sc.z, sh.z));
                    v.w = lrelu(fmaf(a.w * d, sc.w, sh.w));
                }
            }
            Is4[i] = v;
        }
    }
    __syncthreads();

    const int ct = tid & 15, rt = tid >> 4;
    float acc[RPT][CPT];
    #pragma unroll
    for (int j = 0; j < RPT; j++)
        #pragma unroll
        for (int c = 0; c < CPT; c++) acc[j][c] = 0.f;

    const float* isbase = Is + (rt * RPT) * K;
    #pragma unroll 4
    for (int k4 = 0; k4 < K / 4; ++k4) {
        float a[RPT][4];
        #pragma unroll
        for (int j = 0; j < RPT; j++) {
            float4 t4 = *(const float4*)(isbase + j * K + k4 * 4);
            a[j][0] = t4.x; a[j][1] = t4.y; a[j][2] = t4.z; a[j][3] = t4.w;
        }
        #pragma unroll
        for (int kk = 0; kk < 4; kk++) {
            float w[CPT];
            const float4* wr = (const float4*)(Ws + (k4 * 4 + kk) * NC + ct * CPT);
            #pragma unroll
            for (int q = 0; q < CPT / 4; q++) {
                float4 w4 = wr[q];
                w[q * 4 + 0] = w4.x; w[q * 4 + 1] = w4.y;
                w[q * 4 + 2] = w4.z; w[q * 4 + 3] = w4.w;
            }
            #pragma unroll
            for (int j = 0; j < RPT; j++)
                #pragma unroll
                for (int c = 0; c < CPT; c++)
                    acc[j][c] = fmaf(a[j][kk], w[c], acc[j][c]);
        }
    }

    if (MODE == 1) {
        float bl[CPT];
        #pragma unroll
        for (int c = 0; c < CPT; c++) bl[c] = __ldg(&bias[ct * CPT + c]);
        #pragma unroll
        for (int j = 0; j < RPT; j++) {
            int gr = row0 + rt * RPT + j;
            if (gr < NN) {
                #pragma unroll
                for (int c = 0; c < CPT; c++) acc[j][c] += bl[c];
                float4* o = (float4*)(g_h1 + (size_t)gr * NC + ct * CPT);
                #pragma unroll
                for (int q = 0; q < CPT / 4; q++)
                    o[q] = make_float4(acc[j][q * 4 + 0], acc[j][q * 4 + 1],
                                       acc[j][q * 4 + 2], acc[j][q * 4 + 3]);
            } else {
                #pragma unroll
                for (int c = 0; c < CPT; c++) acc[j][c] = 0.f;
            }
        }
        __syncthreads();
        float* ssum = Is;
        float* ssq = Is + NC;
        if (tid < 2 * NC) Is[tid] = 0.f;
        __syncthreads();
        #pragma unroll
        for (int c = 0; c < CPT; c++) {
            float sv = 0.f, sq = 0.f;
            #pragma unroll
            for (int j = 0; j < RPT; j++) { sv += acc[j][c]; sq += acc[j][c] * acc[j][c]; }
            atomicAdd(&ssum[ct * CPT + c], sv);
            atomicAdd(&ssq[ct * CPT + c], sq);
        }
        __syncthreads();
        if (tid < NC) {
            atomicAdd(&g_stats[tid], ssum[tid]);
            atomicAdd(&g_stats[128 + tid], ssq[tid]);
        }
    } else {
        float* o0 = (MODE == 2) ? g_u2 : g_u3;
        #pragma unroll
        for (int j = 0; j < RPT; j++) {
            int gr = row0 + rt * RPT + j;
            if (gr >= NN) continue;
            float d = __ldg((const float*)&g_dinv[gr]);
            ((float4*)(o0 + (size_t)gr * NC))[ct] =
                make_float4(acc[j][0] * d, acc[j][1] * d, acc[j][2] * d, acc[j][3] * d);
        }
    }
}

__global__ void k_final1(const float* __restrict__ g1, const float* __restrict__ be1) {
    int c = threadIdx.x;  // 128
    float mean = g_stats[c] * (1.0f / NN);
    float var = g_stats[128 + c] * (1.0f / NN) - mean * mean;
    float sc = rsqrtf(var + EPS_BN) * __ldg(&g1[c]);
    g_stats[256 + c] = sc;
    g_stats[384 + c] = __ldg(&be1[c]) - mean * sc;
}

// stats over h2 = dinv*acc2 + b2
__global__ void k_stats2(const float* __restrict__ b2) {
    __shared__ float ssum[64], ssq[64];
    int tid = threadIdx.x;
    if (tid < 64) ssum[tid] = 0.f;
    else if (tid < 128) ssq[tid - 64] = 0.f;
    __syncthreads();
    int c4 = tid & 15;
    int rs = tid >> 4;
    float4 b = __ldg((const float4*)b2 + c4);
    float4 s = make_float4(0, 0, 0, 0), q = make_float4(0, 0, 0, 0);
    for (int r = blockIdx.x * 16 + rs; r < NN; r += gridDim.x * 16) {
        float d = g_dinv[r];
        float4 a = ((const float4*)g_acc2)[r * 16 + c4];
        float vx = fmaf(a.x, d, b.x), vy = fmaf(a.y, d, b.y);
        float vz = fmaf(a.z, d, b.z), vw = fmaf(a.w, d, b.w);
        s.x += vx; s.y += vy; s.z += vz; s.w += vw;
        q.x += vx * vx; q.y += vy * vy; q.z += vz * vz; q.w += vw * vw;
    }
    atomicAdd(&ssum[c4 * 4 + 0], s.x); atomicAdd(&ssum[c4 * 4 + 1], s.y);
    atomicAdd(&ssum[c4 * 4 + 2], s.z); atomicAdd(&ssum[c4 * 4 + 3], s.w);
    atomicAdd(&ssq[c4 * 4 + 0], q.x);  atomicAdd(&ssq[c4 * 4 + 1], q.y);
    atomicAdd(&ssq[c4 * 4 + 2], q.z);  atomicAdd(&ssq[c4 * 4 + 3], q.w);
    __syncthreads();
    if (tid < 64) {
        atomicAdd(&g_stats[512 + tid], ssum[tid]);
        atomicAdd(&g_stats[576 + tid], ssq[tid]);
    }
}

__global__ void k_final2(const float* __restrict__ g2, const float* __restrict__ be2,
                         const float* __restrict__ b2) {
    int c = threadIdx.x;  // 64
    float mean = g_stats[512 + c] * (1.0f / NN);
    float var = g_stats[576 + c] * (1.0f / NN) - mean * mean;
    float sc = rsqrtf(var + EPS_BN) * __ldg(&g2[c]);
    g_stats[640 + c] = sc;
    g_stats[704 + c] = __ldg(&be2[c]) + (__ldg(&b2[c]) - mean) * sc;
}

// ---------------- launcher ----------------
extern "C" void kernel_launch(void* const* d_in, const int* in_sizes, int n_in,
                              void* d_out, int out_size) {
    const float* x  = (const float*)d_in[0];
    const int* ei   = (const int*)d_in[1];
    const float* W1 = (const float*)d_in[2];
    const float* b1 = (const float*)d_in[3];
    const float* g1 = (const float*)d_in[4];
    const float* be1= (const float*)d_in[5];
    const float* W2 = (const float*)d_in[6];
    const float* b2 = (const float*)d_in[7];
    const float* g2 = (const float*)d_in[8];
    const float* be2= (const float*)d_in[9];
    const float* W3 = (const float*)d_in[10];
    const float* b3 = (const float*)d_in[11];

    const int nE = in_sizes[1] / 2;
    const int* src = ei;
    const int* dst = ei + nE;

    // CSR build
    k_init<<<(NN + 255) / 256, 256>>>();
    k_deg<<<(nE + 255) / 256, 256>>>(dst, nE);
    k_scan1<<<NBLK, 256>>>();
    k_scan2<<<1, 256>>>();
    k_scan3<<<NBLK, 256>>>();
    k_fill<<<(nE + 255) / 256, 256>>>(src, dst, nE);
    k_prep<<<(NN * 16 + 255) / 256, 256>>>(x);

    // layer 1 (aggregate at 64 ch BEFORE GEMM: A(xW) == (Ax)W)
    k_gather<1><<<(NN * 16 + 255) / 256, 256>>>(nullptr, nullptr);
    k_gemm<64, 128, 4, 1><<<(NN + 63) / 64, 256>>>(W1, b1);
    k_final1<<<1, 128>>>(g1, be1);

    // layer 2
    k_gemm<128, 64, 2, 2><<<(NN + 31) / 32, 256>>>(W2, nullptr);
    k_gather<2><<<(NN * 16 + 255) / 256, 256>>>(nullptr, nullptr);
    k_stats2<<<256, 256>>>(b2);
    k_final2<<<1, 64>>>(g2, be2, b2);

    // layer 3
    k_gemm<64, 64, 4, 3><<<(NN + 63) / 64, 256>>>(W3, nullptr);
    k_gather<3><<<(NN * 16 + 255) / 256, 256>>>((float*)d_out, b3);
}